// round 8
// baseline (speedup 1.0000x reference)
#include <cuda_runtime.h>
#include <cuda_bf16.h>
#include <math.h>
#include <stdint.h>

// Problem constants
#define NN   102400      // nodes
#define EE   1228800     // edges
#define NB   2048        // graphs
#define TT   50          // nodes per graph
#define EPG  600         // edges per graph
#define KIN  576         // IN + POS
#define HH   512         // hidden / out
#define POSD 64

#define CH   64          // channels per aggregation block
#define SAPAD 40         // smem row stride in bf16 (conflict-free frag loads)
#define WSTR 576         // global stride of pre-split weight rows [n][k]

// ---------------- scratch (static device globals) ---------------------------
__device__ uint16_t g_ahi[(size_t)NN * KIN];   // activation hi (bf16 bits)
__device__ uint16_t g_alo[(size_t)NN * KIN];   // activation lo
__device__ uint16_t g_whi[4][(size_t)HH * WSTR];  // weights [n][k] hi
__device__ uint16_t g_wlo[4][(size_t)HH * WSTR];  // weights [n][k] lo
__device__ float g_t [(size_t)NN * HH];
__device__ float g_p1[(size_t)NN * HH];
__device__ float g_p2[(size_t)NN * HH];
__device__ float g_p3[(size_t)NN * HH];
__device__ float g_norm[EE];
__device__ float g_dinv[NN];
__device__ float g_deg [NN];
__device__ float g_stats[2 * HH];
__device__ float g_scale[3 * HH];
__device__ float g_shift[3 * HH];

// ---------------- helpers ---------------------------------------------------
__device__ __forceinline__ void split_bf16(float v, uint16_t& h, uint16_t& l)
{
    __nv_bfloat16 hb = __float2bfloat16(v);
    h = __bfloat16_as_ushort(hb);
    l = __bfloat16_as_ushort(__float2bfloat16(v - __bfloat162float(hb)));
}
__device__ __forceinline__ void mma_bf16(float* c, const uint32_t* a,
                                         uint32_t b0, uint32_t b1)
{
    asm volatile(
        "mma.sync.aligned.m16n8k16.row.col.f32.bf16.bf16.f32 "
        "{%0,%1,%2,%3}, {%4,%5,%6,%7}, {%8,%9}, {%0,%1,%2,%3};"
        : "+f"(c[0]), "+f"(c[1]), "+f"(c[2]), "+f"(c[3])
        : "r"(a[0]), "r"(a[1]), "r"(a[2]), "r"(a[3]), "r"(b0), "r"(b1));
}

// ---------------- concat x || posemb[pos] -> split bf16 ---------------------
__global__ void concat_split_k(const float* __restrict__ x, const int* __restrict__ pos,
                               const float* __restrict__ posemb)
{
    int node = blockIdx.x;
    int j = threadIdx.x;
    float v;
    if (j < HH) v = x[(size_t)node * HH + j];
    else        v = posemb[pos[node] * POSD + (j - HH)];
    uint16_t h, l;
    split_bf16(v, h, l);
    g_ahi[(size_t)node * KIN + j] = h;
    g_alo[(size_t)node * KIN + j] = l;
}

// ---------------- degree / normalization ------------------------------------
__global__ void deg_init_k()
{
    int i = blockIdx.x * blockDim.x + threadIdx.x;
    if (i < NN) g_deg[i] = 1.0f;
}
__global__ void deg_acc_k(const int* __restrict__ dst, const float* __restrict__ w)
{
    int e = blockIdx.x * blockDim.x + threadIdx.x;
    if (e < EE) atomicAdd(&g_deg[dst[e]], w[e]);
}
__global__ void dinv_k()
{
    int i = blockIdx.x * blockDim.x + threadIdx.x;
    if (i < NN) g_dinv[i] = rsqrtf(g_deg[i]);
}
__global__ void norm_k(const int* __restrict__ src, const int* __restrict__ dst,
                       const float* __restrict__ w)
{
    int e = blockIdx.x * blockDim.x + threadIdx.x;
    if (e < EE) g_norm[e] = g_dinv[src[e]] * w[e] * g_dinv[dst[e]];
}

// ---------------- weight prep: W[k][n] fp32 -> [n][k] bf16 hi/lo -----------
template<int L, int KDIM>
__global__ void wprep_k(const float* __restrict__ W)
{
    int n = blockIdx.x;
    for (int k = threadIdx.x; k < KDIM; k += 256) {
        float v = W[(size_t)k * HH + n];
        uint16_t h, l;
        split_bf16(v, h, l);
        g_whi[L][(size_t)n * WSTR + k] = h;
        g_wlo[L][(size_t)n * WSTR + k] = l;
    }
}

// ---------------- activation split: p -> bn+relu -> bf16 hi/lo -------------
template<int SRCL>
__global__ void asplit_k()
{
    const float* src = (SRCL == 0) ? g_p1 : g_p2;
    size_t idx = ((size_t)blockIdx.x * blockDim.x + threadIdx.x) * 4;
    int j = (int)(idx & (HH - 1));
    float4 v = *(const float4*)(src + idx);
    float4 s = *(const float4*)(g_scale + SRCL * HH + j);
    float4 h = *(const float4*)(g_shift + SRCL * HH + j);
    float a0 = fmaxf(fmaf(v.x, s.x, h.x), 0.f);
    float a1 = fmaxf(fmaf(v.y, s.y, h.y), 0.f);
    float a2 = fmaxf(fmaf(v.z, s.z, h.z), 0.f);
    float a3 = fmaxf(fmaf(v.w, s.w, h.w), 0.f);
    ushort4 uh, ul;
    split_bf16(a0, uh.x, ul.x);
    split_bf16(a1, uh.y, ul.y);
    split_bf16(a2, uh.z, ul.z);
    split_bf16(a3, uh.w, ul.w);
    *(ushort4*)(g_ahi + idx) = uh;
    *(ushort4*)(g_alo + idx) = ul;
}

// ---------------- residual combine -> bf16 hi/lo ---------------------------
__global__ void combine_split_k()
{
    size_t idx = ((size_t)blockIdx.x * blockDim.x + threadIdx.x) * 4;
    int j = (int)(idx & (HH - 1));
    float4 a = *(const float4*)(g_p1 + idx);
    float4 b = *(const float4*)(g_p2 + idx);
    float4 c = *(const float4*)(g_p3 + idx);
    float4 s, h;
    float r0, r1, r2, r3;
    s = *(const float4*)(g_scale + j);       h = *(const float4*)(g_shift + j);
    r0 = fmaxf(fmaf(a.x, s.x, h.x), 0.f);
    r1 = fmaxf(fmaf(a.y, s.y, h.y), 0.f);
    r2 = fmaxf(fmaf(a.z, s.z, h.z), 0.f);
    r3 = fmaxf(fmaf(a.w, s.w, h.w), 0.f);
    s = *(const float4*)(g_scale + HH + j);  h = *(const float4*)(g_shift + HH + j);
    r0 += fmaxf(fmaf(b.x, s.x, h.x), 0.f);
    r1 += fmaxf(fmaf(b.y, s.y, h.y), 0.f);
    r2 += fmaxf(fmaf(b.z, s.z, h.z), 0.f);
    r3 += fmaxf(fmaf(b.w, s.w, h.w), 0.f);
    s = *(const float4*)(g_scale + 2*HH + j); h = *(const float4*)(g_shift + 2*HH + j);
    r0 += fmaxf(fmaf(c.x, s.x, h.x), 0.f);
    r1 += fmaxf(fmaf(c.y, s.y, h.y), 0.f);
    r2 += fmaxf(fmaf(c.z, s.z, h.z), 0.f);
    r3 += fmaxf(fmaf(c.w, s.w, h.w), 0.f);
    ushort4 uh, ul;
    split_bf16(r0, uh.x, ul.x);
    split_bf16(r1, uh.y, ul.y);
    split_bf16(r2, uh.z, ul.z);
    split_bf16(r3, uh.w, ul.w);
    *(ushort4*)(g_ahi + idx) = uh;
    *(ushort4*)(g_alo + idx) = ul;
}

// ---------------- split-bf16 HMMA GEMM, 128x64 tile -------------------------
// C[128 x 64/CTA] = A[.,KDIM] @ W  via hi*hi + hi*lo + lo*hi, fp32 accum.
// 8 warps: warp tile 32x32 (wm 0..3, wn 0..1). ~95 regs -> 2 CTAs/SM.
// MODE 0: C -> g_t ; MODE 1: out = tanh(acc + bias). WL = weight table index.
template<int MODE, int KDIM, int WL>
__global__ void __launch_bounds__(256) gemm_hmma(
    float* __restrict__ outC, const float* __restrict__ bias)
{
    __shared__ uint16_t sAhi[128 * SAPAD];
    __shared__ uint16_t sAlo[128 * SAPAD];
    __shared__ uint16_t sBhi[64 * SAPAD];
    __shared__ uint16_t sBlo[64 * SAPAD];

    const int tid  = threadIdx.x;
    const int wid  = tid >> 5;
    const int lane = tid & 31;
    const int g    = lane >> 2;
    const int tig  = lane & 3;
    const int wm   = wid & 3;          // warp m-tile (32 rows)
    const int wn   = wid >> 2;         // warp n-tile (32 cols)

    const int n0 = blockIdx.x * 64;
    const size_t rowBase = (size_t)blockIdx.y * 128;
    const uint16_t* Whi = g_whi[WL];
    const uint16_t* Wlo = g_wlo[WL];

    // A staging: 128x32 bf16 = 512 uint4 -> 2/thread; B: 64x32 = 256 -> 1/thread
    const int aR0 = tid >> 2,        aQ0 = tid & 3;
    const int aR1 = (tid + 256) >> 2, aQ1 = tid & 3;
    const int bR  = tid >> 2,        bQ  = tid & 3;   // rows 0..63

    float acc[2][4][4];
    #pragma unroll
    for (int fm = 0; fm < 2; ++fm)
        #pragma unroll
        for (int fn = 0; fn < 4; ++fn)
            #pragma unroll
            for (int q = 0; q < 4; ++q) acc[fm][fn][q] = 0.f;

    constexpr int CHUNKS = KDIM / 32;
    uint4 rAhi[2], rAlo[2], rBhi, rBlo;

    // prologue: load chunk 0
    {
        const size_t a0 = (rowBase + aR0) * KDIM + aQ0 * 8;
        const size_t a1 = (rowBase + aR1) * KDIM + aQ1 * 8;
        const size_t b0 = (size_t)(n0 + bR) * WSTR + bQ * 8;
        rAhi[0] = *(const uint4*)(g_ahi + a0); rAhi[1] = *(const uint4*)(g_ahi + a1);
        rAlo[0] = *(const uint4*)(g_alo + a0); rAlo[1] = *(const uint4*)(g_alo + a1);
        rBhi = *(const uint4*)(Whi + b0);
        rBlo = *(const uint4*)(Wlo + b0);
    }

    for (int c = 0; c < CHUNKS; ++c) {
        *(uint4*)&sAhi[aR0 * SAPAD + aQ0 * 8] = rAhi[0];
        *(uint4*)&sAhi[aR1 * SAPAD + aQ1 * 8] = rAhi[1];
        *(uint4*)&sAlo[aR0 * SAPAD + aQ0 * 8] = rAlo[0];
        *(uint4*)&sAlo[aR1 * SAPAD + aQ1 * 8] = rAlo[1];
        *(uint4*)&sBhi[bR * SAPAD + bQ * 8] = rBhi;
        *(uint4*)&sBlo[bR * SAPAD + bQ * 8] = rBlo;
        __syncthreads();

        // issue next-chunk loads early (hide gmem latency under MMA)
        if (c + 1 < CHUNKS) {
            const int k0 = (c + 1) * 32;
            const size_t a0 = (rowBase + aR0) * KDIM + k0 + aQ0 * 8;
            const size_t a1 = (rowBase + aR1) * KDIM + k0 + aQ1 * 8;
            const size_t b0 = (size_t)(n0 + bR) * WSTR + k0 + bQ * 8;
            rAhi[0] = *(const uint4*)(g_ahi + a0); rAhi[1] = *(const uint4*)(g_ahi + a1);
            rAlo[0] = *(const uint4*)(g_alo + a0); rAlo[1] = *(const uint4*)(g_alo + a1);
            rBhi = *(const uint4*)(Whi + b0);
            rBlo = *(const uint4*)(Wlo + b0);
        }

        #pragma unroll
        for (int ks = 0; ks < 2; ++ks) {
            const int kc = ks * 16 + 2 * tig;
            uint32_t af[2][2][4];   // [hi/lo][fm][reg]
            #pragma unroll
            for (int fm = 0; fm < 2; ++fm) {
                int r0 = (wm * 32 + fm * 16 + g) * SAPAD;
                int r1 = r0 + 8 * SAPAD;
                af[0][fm][0] = *(uint32_t*)&sAhi[r0 + kc];
                af[0][fm][1] = *(uint32_t*)&sAhi[r1 + kc];
                af[0][fm][2] = *(uint32_t*)&sAhi[r0 + kc + 8];
                af[0][fm][3] = *(uint32_t*)&sAhi[r1 + kc + 8];
                af[1][fm][0] = *(uint32_t*)&sAlo[r0 + kc];
                af[1][fm][1] = *(uint32_t*)&sAlo[r1 + kc];
                af[1][fm][2] = *(uint32_t*)&sAlo[r0 + kc + 8];
                af[1][fm][3] = *(uint32_t*)&sAlo[r1 + kc + 8];
            }
            #pragma unroll
            for (int fn = 0; fn < 4; ++fn) {
                int bn = (wn * 32 + fn * 8 + g) * SAPAD;
                uint32_t bh0 = *(uint32_t*)&sBhi[bn + kc];
                uint32_t bh1 = *(uint32_t*)&sBhi[bn + kc + 8];
                uint32_t bl0 = *(uint32_t*)&sBlo[bn + kc];
                uint32_t bl1 = *(uint32_t*)&sBlo[bn + kc + 8];
                #pragma unroll
                for (int fm = 0; fm < 2; ++fm) {
                    mma_bf16(acc[fm][fn], af[0][fm], bh0, bh1);   // hi*hi
                    mma_bf16(acc[fm][fn], af[0][fm], bl0, bl1);   // hi*lo
                    mma_bf16(acc[fm][fn], af[1][fm], bh0, bh1);   // lo*hi
                }
            }
        }
        __syncthreads();
    }

    // ---- epilogue ----------------------------------------------------------
    float* Cout = (MODE == 0) ? g_t : outC;
    #pragma unroll
    for (int fm = 0; fm < 2; ++fm) {
        size_t r0 = rowBase + wm * 32 + fm * 16 + g;
        size_t r1 = r0 + 8;
        #pragma unroll
        for (int fn = 0; fn < 4; ++fn) {
            int col = n0 + wn * 32 + fn * 8 + 2 * tig;
            float2 v0, v1;
            if (MODE == 0) {
                v0.x = acc[fm][fn][0]; v0.y = acc[fm][fn][1];
                v1.x = acc[fm][fn][2]; v1.y = acc[fm][fn][3];
            } else {
                float bx = bias[col], by = bias[col + 1];
                v0.x = tanhf(acc[fm][fn][0] + bx);
                v0.y = tanhf(acc[fm][fn][1] + by);
                v1.x = tanhf(acc[fm][fn][2] + bx);
                v1.y = tanhf(acc[fm][fn][3] + by);
            }
            *(float2*)(Cout + r0 * HH + col) = v0;
            *(float2*)(Cout + r1 * HH + col) = v1;
        }
    }
}

// ---------------- per-graph aggregation -------------------------------------
template<int L>
__global__ void __launch_bounds__(64) agg_k(
    const int* __restrict__ src, const int* __restrict__ dst,
    const float* __restrict__ bias)
{
    __shared__ float sIn [TT * CH];
    __shared__ float sAcc[TT * CH];
    __shared__ float sNorm[EPG];
    __shared__ float sSelf[TT];
    __shared__ int   sSrc[EPG];
    __shared__ int   sDst[EPG];

    float* pout = (L == 0) ? g_p1 : (L == 1) ? g_p2 : g_p3;

    const int b   = blockIdx.x;
    const int c0  = blockIdx.y * CH;
    const int tid = threadIdx.x;

    const float* base = g_t + (size_t)b * TT * HH + c0;
    for (int i = tid; i < TT * CH; i += 64) {
        int node = i / CH, c = i & (CH - 1);
        sIn[i]  = base[(size_t)node * HH + c];
        sAcc[i] = 0.f;
    }
    for (int e = tid; e < EPG; e += 64) {
        sSrc[e]  = src[b * EPG + e] - b * TT;
        sDst[e]  = dst[b * EPG + e] - b * TT;
        sNorm[e] = g_norm[b * EPG + e];
    }
    for (int i = tid; i < TT; i += 64) {
        float d = g_dinv[b * TT + i];
        sSelf[i] = d * d;
    }
    __syncthreads();

    const int c = tid;
    #pragma unroll 4
    for (int e = 0; e < EPG; ++e) {
        sAcc[sDst[e] * CH + c] += sIn[sSrc[e] * CH + c] * sNorm[e];
    }

    const float bc = bias[c0 + c];
    float sum = 0.f, sq = 0.f;
    for (int node = 0; node < TT; ++node) {
        float v = sAcc[node * CH + c] + sIn[node * CH + c] * sSelf[node] + bc;
        pout[(size_t)(b * TT + node) * HH + c0 + c] = v;
        sum += v;
        sq  += v * v;
    }
    atomicAdd(&g_stats[c0 + c], sum);
    atomicAdd(&g_stats[HH + c0 + c], sq);
}

// ---------------- BN finalize ------------------------------------------------
template<int L>
__global__ void bnfinal_k(const float* __restrict__ g, const float* __restrict__ be)
{
    int c = threadIdx.x;
    float s = g_stats[c], sq = g_stats[HH + c];
    const float inv = 1.0f / (float)NN;
    float mean = s * inv;
    float var  = sq * inv - mean * mean;
    float rstd = rsqrtf(var + 1e-5f);
    float scl  = g[c] * rstd;
    g_scale[L * HH + c] = scl;
    g_shift[L * HH + c] = fmaf(-mean, scl, be[c]);
    g_stats[c] = 0.f;
    g_stats[HH + c] = 0.f;
}

// ---------------- host driver ------------------------------------------------
extern "C" void kernel_launch(void* const* d_in, const int* in_sizes, int n_in,
                              void* d_out, int out_size)
{
    (void)in_sizes; (void)n_in; (void)out_size;

    const float* x      = (const float*)d_in[0];
    const int*   eidx   = (const int*)  d_in[1];
    const int*   esrc   = eidx;
    const int*   edst   = eidx + EE;
    const float* ew     = (const float*)d_in[2];
    const int*   pos    = (const int*)  d_in[3];
    const float* posemb = (const float*)d_in[4];
    const float* W1 = (const float*)d_in[5];
    const float* b1 = (const float*)d_in[6];
    const float* g1 = (const float*)d_in[7];
    const float* be1= (const float*)d_in[8];
    const float* W2 = (const float*)d_in[9];
    const float* b2 = (const float*)d_in[10];
    const float* g2 = (const float*)d_in[11];
    const float* be2= (const float*)d_in[12];
    const float* W3 = (const float*)d_in[13];
    const float* b3 = (const float*)d_in[14];
    const float* g3 = (const float*)d_in[15];
    const float* be3= (const float*)d_in[16];
    const float* Wl = (const float*)d_in[17];
    const float* bl = (const float*)d_in[18];
    float* out = (float*)d_out;

    dim3 aGrid(NB, HH / CH);          // (2048, 8)
    dim3 gGrid(HH / 64, NN / 128);    // (8, 800)
    const int SPLIT_BLOCKS = (NN * HH / 4) / 256;   // 51200

    // 0) concat(split) + normalization + weight prep
    concat_split_k<<<NN, KIN>>>(x, pos, posemb);
    deg_init_k<<<(NN + 255) / 256, 256>>>();
    deg_acc_k<<<(EE + 255) / 256, 256>>>(edst, ew);
    dinv_k<<<(NN + 255) / 256, 256>>>();
    norm_k<<<(EE + 255) / 256, 256>>>(esrc, edst, ew);
    wprep_k<0, KIN><<<HH, 256>>>(W1);
    wprep_k<1, HH><<<HH, 256>>>(W2);
    wprep_k<2, HH><<<HH, 256>>>(W3);
    wprep_k<3, HH><<<HH, 256>>>(Wl);

    // layer 1
    gemm_hmma<0, KIN, 0><<<gGrid, 256>>>(nullptr, nullptr);
    agg_k<0><<<aGrid, 64>>>(esrc, edst, b1);
    bnfinal_k<0><<<1, HH>>>(g1, be1);
    asplit_k<0><<<SPLIT_BLOCKS, 256>>>();

    // layer 2
    gemm_hmma<0, HH, 1><<<gGrid, 256>>>(nullptr, nullptr);
    agg_k<1><<<aGrid, 64>>>(esrc, edst, b2);
    bnfinal_k<1><<<1, HH>>>(g2, be2);
    asplit_k<1><<<SPLIT_BLOCKS, 256>>>();

    // layer 3
    gemm_hmma<0, HH, 2><<<gGrid, 256>>>(nullptr, nullptr);
    agg_k<2><<<aGrid, 64>>>(esrc, edst, b3);
    bnfinal_k<2><<<1, HH>>>(g3, be3);

    // residual combine (split) + final head
    combine_split_k<<<SPLIT_BLOCKS, 256>>>();
    gemm_hmma<1, HH, 3><<<gGrid, 256>>>(out, bl);
}

// round 10
// speedup vs baseline: 1.0606x; 1.0606x over previous
#include <cuda_runtime.h>
#include <cuda_bf16.h>
#include <math.h>
#include <stdint.h>

// Problem constants
#define NN   102400      // nodes
#define EE   1228800     // edges
#define NB   2048        // graphs
#define TT   50          // nodes per graph
#define EPG  600         // edges per graph
#define KIN  576         // IN + POS
#define HH   512         // hidden / out
#define POSD 64

#define CH   64          // channels per aggregation block
#define WSTR 576         // global stride of pre-split weight rows [n][k]

// pipeline stage layout (bytes): 4 arrays of 128 rows x 16 bf16 (32B/row)
#define ARR_B  4096              // bytes per array
#define STG_B  16384             // bytes per stage (Ahi|Alo|Bhi|Blo)
// 3 stages x 16384 = 49152 B static shared (fits 48KB limit exactly)

// ---------------- scratch (static device globals) ---------------------------
__device__ uint16_t g_ahi[(size_t)NN * KIN];   // activation hi (bf16 bits)
__device__ uint16_t g_alo[(size_t)NN * KIN];   // activation lo
__device__ uint16_t g_whi[4][(size_t)HH * WSTR];  // weights [n][k] hi
__device__ uint16_t g_wlo[4][(size_t)HH * WSTR];  // weights [n][k] lo
__device__ float g_t [(size_t)NN * HH];
__device__ float g_p1[(size_t)NN * HH];
__device__ float g_p2[(size_t)NN * HH];
__device__ float g_p3[(size_t)NN * HH];
__device__ float g_norm[EE];
__device__ float g_dinv[NN];
__device__ float g_deg [NN];
__device__ float g_stats[2 * HH];
__device__ float g_scale[3 * HH];
__device__ float g_shift[3 * HH];

// ---------------- helpers ---------------------------------------------------
__device__ __forceinline__ void split_bf16(float v, uint16_t& h, uint16_t& l)
{
    __nv_bfloat16 hb = __float2bfloat16(v);
    h = __bfloat16_as_ushort(hb);
    l = __bfloat16_as_ushort(__float2bfloat16(v - __bfloat162float(hb)));
}
__device__ __forceinline__ void mma_bf16(float* c, const uint32_t* a,
                                         uint32_t b0, uint32_t b1)
{
    asm volatile(
        "mma.sync.aligned.m16n8k16.row.col.f32.bf16.bf16.f32 "
        "{%0,%1,%2,%3}, {%4,%5,%6,%7}, {%8,%9}, {%0,%1,%2,%3};"
        : "+f"(c[0]), "+f"(c[1]), "+f"(c[2]), "+f"(c[3])
        : "r"(a[0]), "r"(a[1]), "r"(a[2]), "r"(a[3]), "r"(b0), "r"(b1));
}
__device__ __forceinline__ void cpa16(uint32_t s, const void* g)
{
    asm volatile("cp.async.ca.shared.global [%0], [%1], 16;" :: "r"(s), "l"(g));
}
#define CPA_COMMIT() asm volatile("cp.async.commit_group;" ::: "memory")
template<int N> __device__ __forceinline__ void cpa_wait()
{
    asm volatile("cp.async.wait_group %0;" :: "n"(N) : "memory");
}
// swizzled byte offset within one 128x16-bf16 array: row r, 4B-word w (0..7)
__device__ __forceinline__ int swb(int r, int w)
{
    return ((r * 2 + ((w >> 2) ^ ((r >> 2) & 1))) << 4) | ((w & 3) << 2);
}

// ---------------- concat x || posemb[pos] -> split bf16 ---------------------
__global__ void concat_split_k(const float* __restrict__ x, const int* __restrict__ pos,
                               const float* __restrict__ posemb)
{
    int node = blockIdx.x;
    int j = threadIdx.x;
    float v;
    if (j < HH) v = x[(size_t)node * HH + j];
    else        v = posemb[pos[node] * POSD + (j - HH)];
    uint16_t h, l;
    split_bf16(v, h, l);
    g_ahi[(size_t)node * KIN + j] = h;
    g_alo[(size_t)node * KIN + j] = l;
}

// ---------------- degree / normalization ------------------------------------
__global__ void deg_init_k()
{
    int i = blockIdx.x * blockDim.x + threadIdx.x;
    if (i < NN) g_deg[i] = 1.0f;
}
__global__ void deg_acc_k(const int* __restrict__ dst, const float* __restrict__ w)
{
    int e = blockIdx.x * blockDim.x + threadIdx.x;
    if (e < EE) atomicAdd(&g_deg[dst[e]], w[e]);
}
__global__ void dinv_k()
{
    int i = blockIdx.x * blockDim.x + threadIdx.x;
    if (i < NN) g_dinv[i] = rsqrtf(g_deg[i]);
}
__global__ void norm_k(const int* __restrict__ src, const int* __restrict__ dst,
                       const float* __restrict__ w)
{
    int e = blockIdx.x * blockDim.x + threadIdx.x;
    if (e < EE) g_norm[e] = g_dinv[src[e]] * w[e] * g_dinv[dst[e]];
}

// ---------------- weight prep: W[k][n] fp32 -> [n][k] bf16 hi/lo -----------
template<int L, int KDIM>
__global__ void wprep_k(const float* __restrict__ W)
{
    int n = blockIdx.x;
    for (int k = threadIdx.x; k < KDIM; k += 256) {
        float v = W[(size_t)k * HH + n];
        uint16_t h, l;
        split_bf16(v, h, l);
        g_whi[L][(size_t)n * WSTR + k] = h;
        g_wlo[L][(size_t)n * WSTR + k] = l;
    }
}

// ---------------- activation split: p -> bn+relu -> bf16 hi/lo -------------
template<int SRCL>
__global__ void asplit_k()
{
    const float* src = (SRCL == 0) ? g_p1 : g_p2;
    size_t idx = ((size_t)blockIdx.x * blockDim.x + threadIdx.x) * 4;
    int j = (int)(idx & (HH - 1));
    float4 v = *(const float4*)(src + idx);
    float4 s = *(const float4*)(g_scale + SRCL * HH + j);
    float4 h = *(const float4*)(g_shift + SRCL * HH + j);
    float a0 = fmaxf(fmaf(v.x, s.x, h.x), 0.f);
    float a1 = fmaxf(fmaf(v.y, s.y, h.y), 0.f);
    float a2 = fmaxf(fmaf(v.z, s.z, h.z), 0.f);
    float a3 = fmaxf(fmaf(v.w, s.w, h.w), 0.f);
    ushort4 uh, ul;
    split_bf16(a0, uh.x, ul.x);
    split_bf16(a1, uh.y, ul.y);
    split_bf16(a2, uh.z, ul.z);
    split_bf16(a3, uh.w, ul.w);
    *(ushort4*)(g_ahi + idx) = uh;
    *(ushort4*)(g_alo + idx) = ul;
}

// ---------------- residual combine -> bf16 hi/lo ---------------------------
__global__ void combine_split_k()
{
    size_t idx = ((size_t)blockIdx.x * blockDim.x + threadIdx.x) * 4;
    int j = (int)(idx & (HH - 1));
    float4 a = *(const float4*)(g_p1 + idx);
    float4 b = *(const float4*)(g_p2 + idx);
    float4 c = *(const float4*)(g_p3 + idx);
    float4 s, h;
    float r0, r1, r2, r3;
    s = *(const float4*)(g_scale + j);       h = *(const float4*)(g_shift + j);
    r0 = fmaxf(fmaf(a.x, s.x, h.x), 0.f);
    r1 = fmaxf(fmaf(a.y, s.y, h.y), 0.f);
    r2 = fmaxf(fmaf(a.z, s.z, h.z), 0.f);
    r3 = fmaxf(fmaf(a.w, s.w, h.w), 0.f);
    s = *(const float4*)(g_scale + HH + j);  h = *(const float4*)(g_shift + HH + j);
    r0 += fmaxf(fmaf(b.x, s.x, h.x), 0.f);
    r1 += fmaxf(fmaf(b.y, s.y, h.y), 0.f);
    r2 += fmaxf(fmaf(b.z, s.z, h.z), 0.f);
    r3 += fmaxf(fmaf(b.w, s.w, h.w), 0.f);
    s = *(const float4*)(g_scale + 2*HH + j); h = *(const float4*)(g_shift + 2*HH + j);
    r0 += fmaxf(fmaf(c.x, s.x, h.x), 0.f);
    r1 += fmaxf(fmaf(c.y, s.y, h.y), 0.f);
    r2 += fmaxf(fmaf(c.z, s.z, h.z), 0.f);
    r3 += fmaxf(fmaf(c.w, s.w, h.w), 0.f);
    ushort4 uh, ul;
    split_bf16(r0, uh.x, ul.x);
    split_bf16(r1, uh.y, ul.y);
    split_bf16(r2, uh.z, ul.z);
    split_bf16(r3, uh.w, ul.w);
    *(ushort4*)(g_ahi + idx) = uh;
    *(ushort4*)(g_alo + idx) = ul;
}

// ---------------- split-bf16 HMMA GEMM, 128x128 tile, cp.async 3-stage ------
// C[128 x 128/CTA] = A[.,KDIM] @ W  via hi*hi + hi*lo + lo*hi, fp32 accum.
// Kc=16 per chunk; 48KB static smem; 2 CTAs/SM.
// MODE 0: C -> g_t ; MODE 1: out = tanh(acc + bias). WL = weight table index.
template<int MODE, int KDIM, int WL>
__global__ void __launch_bounds__(256, 2) gemm_hmma(
    float* __restrict__ outC, const float* __restrict__ bias)
{
    __shared__ __align__(16) uint8_t smem3[3 * STG_B];

    const int tid  = threadIdx.x;
    const int wid  = tid >> 5;
    const int lane = tid & 31;
    const int g    = lane >> 2;
    const int tig  = lane & 3;
    const int wm   = wid & 3;          // warp m-tile (32 rows)
    const int wn   = wid >> 2;         // warp n-tile (64 cols)

    const int n0 = blockIdx.x * 128;
    const size_t rowBase = (size_t)blockIdx.y * 128;
    const uint16_t* Whi = g_whi[WL];
    const uint16_t* Wlo = g_wlo[WL];

    const uint32_t smemBase = (uint32_t)__cvta_generic_to_shared(smem3);
    // cp.async coordinates: thread -> (row, 16B-unit)
    const int cr = tid >> 1;
    const int cu = tid & 1;
    const uint32_t cDst = smemBase + (uint32_t)((cr * 2 + (cu ^ ((cr >> 2) & 1))) << 4);
    const size_t aSrc = (rowBase + cr) * KDIM + cu * 8;
    const size_t bSrc = (size_t)(n0 + cr) * WSTR + cu * 8;

    float acc[2][8][4];
    #pragma unroll
    for (int fm = 0; fm < 2; ++fm)
        #pragma unroll
        for (int fn = 0; fn < 8; ++fn)
            #pragma unroll
            for (int q = 0; q < 4; ++q) acc[fm][fn][q] = 0.f;

    constexpr int CHUNKS = KDIM / 16;

    auto issue = [&](int c) {
        if (c < CHUNKS) {
            const int k0 = c * 16;
            const uint32_t sb = cDst + (uint32_t)(c % 3) * STG_B;
            cpa16(sb,              g_ahi + aSrc + k0);
            cpa16(sb + ARR_B,      g_alo + aSrc + k0);
            cpa16(sb + 2 * ARR_B,  Whi + bSrc + k0);
            cpa16(sb + 3 * ARR_B,  Wlo + bSrc + k0);
        }
        CPA_COMMIT();
    };

    issue(0);
    issue(1);

    // fragment smem byte offsets (within an array), fixed per thread
    int offA[2][4], offB[8][2];
    #pragma unroll
    for (int fm = 0; fm < 2; ++fm) {
        int r0 = wm * 32 + fm * 16 + g;
        offA[fm][0] = swb(r0,     tig);
        offA[fm][1] = swb(r0 + 8, tig);
        offA[fm][2] = swb(r0,     tig + 4);
        offA[fm][3] = swb(r0 + 8, tig + 4);
    }
    #pragma unroll
    for (int fn = 0; fn < 8; ++fn) {
        int bn = wn * 64 + fn * 8 + g;
        offB[fn][0] = swb(bn, tig);
        offB[fn][1] = swb(bn, tig + 4);
    }

    for (int c = 0; c < CHUNKS; ++c) {
        issue(c + 2);
        cpa_wait<2>();
        __syncthreads();

        const uint8_t* sb  = smem3 + (c % 3) * STG_B;
        const uint8_t* sAhi = sb;
        const uint8_t* sAlo = sb + ARR_B;
        const uint8_t* sBhi = sb + 2 * ARR_B;
        const uint8_t* sBlo = sb + 3 * ARR_B;

        uint32_t af[2][2][4];
        #pragma unroll
        for (int fm = 0; fm < 2; ++fm)
            #pragma unroll
            for (int q = 0; q < 4; ++q) {
                af[0][fm][q] = *(const uint32_t*)(sAhi + offA[fm][q]);
                af[1][fm][q] = *(const uint32_t*)(sAlo + offA[fm][q]);
            }
        #pragma unroll
        for (int fn = 0; fn < 8; ++fn) {
            uint32_t bh0 = *(const uint32_t*)(sBhi + offB[fn][0]);
            uint32_t bh1 = *(const uint32_t*)(sBhi + offB[fn][1]);
            uint32_t bl0 = *(const uint32_t*)(sBlo + offB[fn][0]);
            uint32_t bl1 = *(const uint32_t*)(sBlo + offB[fn][1]);
            #pragma unroll
            for (int fm = 0; fm < 2; ++fm) {
                mma_bf16(acc[fm][fn], af[0][fm], bh0, bh1);   // hi*hi
                mma_bf16(acc[fm][fn], af[0][fm], bl0, bl1);   // hi*lo
                mma_bf16(acc[fm][fn], af[1][fm], bh0, bh1);   // lo*hi
            }
        }
        __syncthreads();
    }

    // ---- epilogue ----------------------------------------------------------
    float* Cout = (MODE == 0) ? g_t : outC;
    #pragma unroll
    for (int fm = 0; fm < 2; ++fm) {
        size_t r0 = rowBase + wm * 32 + fm * 16 + g;
        size_t r1 = r0 + 8;
        #pragma unroll
        for (int fn = 0; fn < 8; ++fn) {
            int col = n0 + wn * 64 + fn * 8 + 2 * tig;
            float2 v0, v1;
            if (MODE == 0) {
                v0.x = acc[fm][fn][0]; v0.y = acc[fm][fn][1];
                v1.x = acc[fm][fn][2]; v1.y = acc[fm][fn][3];
            } else {
                float bx = bias[col], by = bias[col + 1];
                v0.x = tanhf(acc[fm][fn][0] + bx);
                v0.y = tanhf(acc[fm][fn][1] + by);
                v1.x = tanhf(acc[fm][fn][2] + bx);
                v1.y = tanhf(acc[fm][fn][3] + by);
            }
            *(float2*)(Cout + r0 * HH + col) = v0;
            *(float2*)(Cout + r1 * HH + col) = v1;
        }
    }
}

// ---------------- per-graph aggregation -------------------------------------
template<int L>
__global__ void __launch_bounds__(64) agg_k(
    const int* __restrict__ src, const int* __restrict__ dst,
    const float* __restrict__ bias)
{
    __shared__ float sIn [TT * CH];
    __shared__ float sAcc[TT * CH];
    __shared__ float sNorm[EPG];
    __shared__ float sSelf[TT];
    __shared__ int   sSrc[EPG];
    __shared__ int   sDst[EPG];

    float* pout = (L == 0) ? g_p1 : (L == 1) ? g_p2 : g_p3;

    const int b   = blockIdx.x;
    const int c0  = blockIdx.y * CH;
    const int tid = threadIdx.x;

    const float* base = g_t + (size_t)b * TT * HH + c0;
    for (int i = tid; i < TT * CH; i += 64) {
        int node = i / CH, c = i & (CH - 1);
        sIn[i]  = base[(size_t)node * HH + c];
        sAcc[i] = 0.f;
    }
    for (int e = tid; e < EPG; e += 64) {
        sSrc[e]  = src[b * EPG + e] - b * TT;
        sDst[e]  = dst[b * EPG + e] - b * TT;
        sNorm[e] = g_norm[b * EPG + e];
    }
    for (int i = tid; i < TT; i += 64) {
        float d = g_dinv[b * TT + i];
        sSelf[i] = d * d;
    }
    __syncthreads();

    const int c = tid;
    #pragma unroll 4
    for (int e = 0; e < EPG; ++e) {
        sAcc[sDst[e] * CH + c] += sIn[sSrc[e] * CH + c] * sNorm[e];
    }

    const float bc = bias[c0 + c];
    float sum = 0.f, sq = 0.f;
    for (int node = 0; node < TT; ++node) {
        float v = sAcc[node * CH + c] + sIn[node * CH + c] * sSelf[node] + bc;
        pout[(size_t)(b * TT + node) * HH + c0 + c] = v;
        sum += v;
        sq  += v * v;
    }
    atomicAdd(&g_stats[c0 + c], sum);
    atomicAdd(&g_stats[HH + c0 + c], sq);
}

// ---------------- BN finalize ------------------------------------------------
template<int L>
__global__ void bnfinal_k(const float* __restrict__ g, const float* __restrict__ be)
{
    int c = threadIdx.x;
    float s = g_stats[c], sq = g_stats[HH + c];
    const float inv = 1.0f / (float)NN;
    float mean = s * inv;
    float var  = sq * inv - mean * mean;
    float rstd = rsqrtf(var + 1e-5f);
    float scl  = g[c] * rstd;
    g_scale[L * HH + c] = scl;
    g_shift[L * HH + c] = fmaf(-mean, scl, be[c]);
    g_stats[c] = 0.f;
    g_stats[HH + c] = 0.f;
}

// ---------------- host driver: kernel launches ONLY --------------------------
extern "C" void kernel_launch(void* const* d_in, const int* in_sizes, int n_in,
                              void* d_out, int out_size)
{
    (void)in_sizes; (void)n_in; (void)out_size;

    const float* x      = (const float*)d_in[0];
    const int*   eidx   = (const int*)  d_in[1];
    const int*   esrc   = eidx;
    const int*   edst   = eidx + EE;
    const float* ew     = (const float*)d_in[2];
    const int*   pos    = (const int*)  d_in[3];
    const float* posemb = (const float*)d_in[4];
    const float* W1 = (const float*)d_in[5];
    const float* b1 = (const float*)d_in[6];
    const float* g1 = (const float*)d_in[7];
    const float* be1= (const float*)d_in[8];
    const float* W2 = (const float*)d_in[9];
    const float* b2 = (const float*)d_in[10];
    const float* g2 = (const float*)d_in[11];
    const float* be2= (const float*)d_in[12];
    const float* W3 = (const float*)d_in[13];
    const float* b3 = (const float*)d_in[14];
    const float* g3 = (const float*)d_in[15];
    const float* be3= (const float*)d_in[16];
    const float* Wl = (const float*)d_in[17];
    const float* bl = (const float*)d_in[18];
    float* out = (float*)d_out;

    dim3 aGrid(NB, HH / CH);          // (2048, 8)
    dim3 gGrid(HH / 128, NN / 128);   // (4, 800)
    const int SPLIT_BLOCKS = (NN * HH / 4) / 256;   // 51200

    // prep ordered so gemm1 is launch index 3 (profiled slot)
    concat_split_k<<<NN, KIN>>>(x, pos, posemb);          // 0
    wprep_k<0, KIN><<<HH, 256>>>(W1);                     // 1
    wprep_k<1, HH><<<HH, 256>>>(W2);                      // 2
    gemm_hmma<0, KIN, 0><<<gGrid, 256>>>(nullptr, nullptr);  // 3
    deg_init_k<<<(NN + 255) / 256, 256>>>();              // 4
    deg_acc_k<<<(EE + 255) / 256, 256>>>(edst, ew);       // 5
    dinv_k<<<(NN + 255) / 256, 256>>>();                  // 6
    norm_k<<<(EE + 255) / 256, 256>>>(esrc, edst, ew);    // 7
    wprep_k<2, HH><<<HH, 256>>>(W3);                      // 8
    wprep_k<3, HH><<<HH, 256>>>(Wl);                      // 9

    // layer 1 aggregation + BN
    agg_k<0><<<aGrid, 64>>>(esrc, edst, b1);
    bnfinal_k<0><<<1, HH>>>(g1, be1);
    asplit_k<0><<<SPLIT_BLOCKS, 256>>>();

    // layer 2
    gemm_hmma<0, HH, 1><<<gGrid, 256>>>(nullptr, nullptr);
    agg_k<1><<<aGrid, 64>>>(esrc, edst, b2);
    bnfinal_k<1><<<1, HH>>>(g2, be2);
    asplit_k<1><<<SPLIT_BLOCKS, 256>>>();

    // layer 3
    gemm_hmma<0, HH, 2><<<gGrid, 256>>>(nullptr, nullptr);
    agg_k<2><<<aGrid, 64>>>(esrc, edst, b3);
    bnfinal_k<2><<<1, HH>>>(g3, be3);

    // residual combine + final head
    combine_split_k<<<SPLIT_BLOCKS, 256>>>();
    gemm_hmma<1, HH, 3><<<gGrid, 256>>>(out, bl);
}

// round 11
// speedup vs baseline: 1.0790x; 1.0173x over previous
#include <cuda_runtime.h>
#include <cuda_bf16.h>
#include <math.h>
#include <stdint.h>

// Problem constants
#define NN   102400      // nodes
#define EE   1228800     // edges
#define NB   2048        // graphs
#define TT   50          // nodes per graph
#define EPG  600         // edges per graph
#define KIN  576         // IN + POS
#define HH   512         // hidden / out
#define POSD 64

#define CH   64          // channels per aggregation block
#define WSTR 576         // global stride of pre-split weight rows [n][k]

// pipeline stage layout (bytes): A 128 rows x 16 bf16, B 256 rows x 16 bf16
#define A_HI_OFF 0
#define A_LO_OFF 4096
#define B_HI_OFF 8192
#define B_LO_OFF 16384
#define STG2_B   24576           // bytes per stage
// 2 stages x 24576 = 49152 B static shared (= 48KB limit exactly)

// ---------------- scratch (static device globals) ---------------------------
__device__ uint16_t g_ahi[(size_t)NN * KIN];   // activation hi (bf16 bits)
__device__ uint16_t g_alo[(size_t)NN * KIN];   // activation lo
__device__ uint16_t g_whi[4][(size_t)HH * WSTR];  // weights [n][k] hi
__device__ uint16_t g_wlo[4][(size_t)HH * WSTR];  // weights [n][k] lo
__device__ float g_t [(size_t)NN * HH];
__device__ float g_p1[(size_t)NN * HH];
__device__ float g_p2[(size_t)NN * HH];
__device__ float g_p3[(size_t)NN * HH];
__device__ float g_norm[EE];
__device__ float g_dinv[NN];
__device__ float g_deg [NN];
__device__ float g_stats[2 * HH];
__device__ float g_scale[3 * HH];
__device__ float g_shift[3 * HH];

// ---------------- helpers ---------------------------------------------------
__device__ __forceinline__ void split_bf16(float v, uint16_t& h, uint16_t& l)
{
    __nv_bfloat16 hb = __float2bfloat16(v);
    h = __bfloat16_as_ushort(hb);
    l = __bfloat16_as_ushort(__float2bfloat16(v - __bfloat162float(hb)));
}
__device__ __forceinline__ void mma_bf16(float* c, const uint32_t* a,
                                         uint32_t b0, uint32_t b1)
{
    asm volatile(
        "mma.sync.aligned.m16n8k16.row.col.f32.bf16.bf16.f32 "
        "{%0,%1,%2,%3}, {%4,%5,%6,%7}, {%8,%9}, {%0,%1,%2,%3};"
        : "+f"(c[0]), "+f"(c[1]), "+f"(c[2]), "+f"(c[3])
        : "r"(a[0]), "r"(a[1]), "r"(a[2]), "r"(a[3]), "r"(b0), "r"(b1));
}
__device__ __forceinline__ void cpa16(uint32_t s, const void* g)
{
    asm volatile("cp.async.ca.shared.global [%0], [%1], 16;" :: "r"(s), "l"(g));
}
#define CPA_COMMIT() asm volatile("cp.async.commit_group;" ::: "memory")
template<int N> __device__ __forceinline__ void cpa_wait()
{
    asm volatile("cp.async.wait_group %0;" :: "n"(N) : "memory");
}
// swizzled byte offset within one [rows x 16 bf16] array: row r, 4B-word w (0..7)
__device__ __forceinline__ int swb(int r, int w)
{
    return ((r * 2 + ((w >> 2) ^ ((r >> 2) & 1))) << 4) | ((w & 3) << 2);
}

// ---------------- concat x || posemb[pos] -> split bf16 ---------------------
__global__ void concat_split_k(const float* __restrict__ x, const int* __restrict__ pos,
                               const float* __restrict__ posemb)
{
    int node = blockIdx.x;
    int j = threadIdx.x;
    float v;
    if (j < HH) v = x[(size_t)node * HH + j];
    else        v = posemb[pos[node] * POSD + (j - HH)];
    uint16_t h, l;
    split_bf16(v, h, l);
    g_ahi[(size_t)node * KIN + j] = h;
    g_alo[(size_t)node * KIN + j] = l;
}

// ---------------- degree / normalization ------------------------------------
__global__ void deg_init_k()
{
    int i = blockIdx.x * blockDim.x + threadIdx.x;
    if (i < NN) g_deg[i] = 1.0f;
}
__global__ void deg_acc_k(const int* __restrict__ dst, const float* __restrict__ w)
{
    int e = blockIdx.x * blockDim.x + threadIdx.x;
    if (e < EE) atomicAdd(&g_deg[dst[e]], w[e]);
}
__global__ void dinv_k()
{
    int i = blockIdx.x * blockDim.x + threadIdx.x;
    if (i < NN) g_dinv[i] = rsqrtf(g_deg[i]);
}
__global__ void norm_k(const int* __restrict__ src, const int* __restrict__ dst,
                       const float* __restrict__ w)
{
    int e = blockIdx.x * blockDim.x + threadIdx.x;
    if (e < EE) g_norm[e] = g_dinv[src[e]] * w[e] * g_dinv[dst[e]];
}

// ---------------- weight prep: W[k][n] fp32 -> [n][k] bf16 hi/lo -----------
template<int L, int KDIM>
__global__ void wprep_k(const float* __restrict__ W)
{
    int n = blockIdx.x;
    for (int k = threadIdx.x; k < KDIM; k += 256) {
        float v = W[(size_t)k * HH + n];
        uint16_t h, l;
        split_bf16(v, h, l);
        g_whi[L][(size_t)n * WSTR + k] = h;
        g_wlo[L][(size_t)n * WSTR + k] = l;
    }
}

// ---------------- activation split: p -> bn+relu -> bf16 hi/lo -------------
template<int SRCL>
__global__ void asplit_k()
{
    const float* src = (SRCL == 0) ? g_p1 : g_p2;
    size_t idx = ((size_t)blockIdx.x * blockDim.x + threadIdx.x) * 4;
    int j = (int)(idx & (HH - 1));
    float4 v = *(const float4*)(src + idx);
    float4 s = *(const float4*)(g_scale + SRCL * HH + j);
    float4 h = *(const float4*)(g_shift + SRCL * HH + j);
    float a0 = fmaxf(fmaf(v.x, s.x, h.x), 0.f);
    float a1 = fmaxf(fmaf(v.y, s.y, h.y), 0.f);
    float a2 = fmaxf(fmaf(v.z, s.z, h.z), 0.f);
    float a3 = fmaxf(fmaf(v.w, s.w, h.w), 0.f);
    ushort4 uh, ul;
    split_bf16(a0, uh.x, ul.x);
    split_bf16(a1, uh.y, ul.y);
    split_bf16(a2, uh.z, ul.z);
    split_bf16(a3, uh.w, ul.w);
    *(ushort4*)(g_ahi + idx) = uh;
    *(ushort4*)(g_alo + idx) = ul;
}

// ---------------- residual combine -> bf16 hi/lo ---------------------------
__global__ void combine_split_k()
{
    size_t idx = ((size_t)blockIdx.x * blockDim.x + threadIdx.x) * 4;
    int j = (int)(idx & (HH - 1));
    float4 a = *(const float4*)(g_p1 + idx);
    float4 b = *(const float4*)(g_p2 + idx);
    float4 c = *(const float4*)(g_p3 + idx);
    float4 s, h;
    float r0, r1, r2, r3;
    s = *(const float4*)(g_scale + j);       h = *(const float4*)(g_shift + j);
    r0 = fmaxf(fmaf(a.x, s.x, h.x), 0.f);
    r1 = fmaxf(fmaf(a.y, s.y, h.y), 0.f);
    r2 = fmaxf(fmaf(a.z, s.z, h.z), 0.f);
    r3 = fmaxf(fmaf(a.w, s.w, h.w), 0.f);
    s = *(const float4*)(g_scale + HH + j);  h = *(const float4*)(g_shift + HH + j);
    r0 += fmaxf(fmaf(b.x, s.x, h.x), 0.f);
    r1 += fmaxf(fmaf(b.y, s.y, h.y), 0.f);
    r2 += fmaxf(fmaf(b.z, s.z, h.z), 0.f);
    r3 += fmaxf(fmaf(b.w, s.w, h.w), 0.f);
    s = *(const float4*)(g_scale + 2*HH + j); h = *(const float4*)(g_shift + 2*HH + j);
    r0 += fmaxf(fmaf(c.x, s.x, h.x), 0.f);
    r1 += fmaxf(fmaf(c.y, s.y, h.y), 0.f);
    r2 += fmaxf(fmaf(c.z, s.z, h.z), 0.f);
    r3 += fmaxf(fmaf(c.w, s.w, h.w), 0.f);
    ushort4 uh, ul;
    split_bf16(r0, uh.x, ul.x);
    split_bf16(r1, uh.y, ul.y);
    split_bf16(r2, uh.z, ul.z);
    split_bf16(r3, uh.w, ul.w);
    *(ushort4*)(g_ahi + idx) = uh;
    *(ushort4*)(g_alo + idx) = ul;
}

// ---------------- split-bf16 HMMA GEMM, CTA 128x256, warp tile 64x64 --------
// C = A @ W via hi*hi + hi*lo + lo*hi, fp32 accum. Kc=16, 2-stage cp.async,
// 48KB static smem, 1 CTA/SM. MODE 0: C -> g_t ; MODE 1: out = tanh(acc+bias).
template<int MODE, int KDIM, int WL>
__global__ void __launch_bounds__(256, 1) gemm_hmma(
    float* __restrict__ outC, const float* __restrict__ bias)
{
    __shared__ __align__(16) uint8_t smem2[2 * STG2_B];

    const int tid  = threadIdx.x;
    const int wid  = tid >> 5;
    const int lane = tid & 31;
    const int g    = lane >> 2;
    const int tig  = lane & 3;
    const int wm   = wid >> 2;         // warp m-tile 0..1 (64 rows)
    const int wn   = wid & 3;          // warp n-tile 0..3 (64 cols)

    const int n0 = blockIdx.x * 256;
    const size_t rowBase = (size_t)blockIdx.y * 128;
    const uint16_t* Whi = g_whi[WL];
    const uint16_t* Wlo = g_wlo[WL];

    const uint32_t smemBase = (uint32_t)__cvta_generic_to_shared(smem2);
    // cp.async coordinates: thread -> (row cr, 16B-unit cu)
    const int cr = tid >> 1;
    const int cu = tid & 1;
    const uint32_t dA  = smemBase + (uint32_t)((cr * 2 + (cu ^ ((cr >> 2) & 1))) << 4);
    const int br1 = cr + 128;
    const uint32_t dB0 = smemBase + (uint32_t)((cr * 2 + (cu ^ ((cr >> 2) & 1))) << 4);
    const uint32_t dB1 = smemBase + (uint32_t)((br1 * 2 + (cu ^ ((br1 >> 2) & 1))) << 4);
    const size_t aSrc  = (rowBase + cr) * KDIM + cu * 8;
    const size_t bSrc0 = (size_t)(n0 + cr) * WSTR + cu * 8;
    const size_t bSrc1 = (size_t)(n0 + br1) * WSTR + cu * 8;

    float acc[4][8][4];
    #pragma unroll
    for (int fm = 0; fm < 4; ++fm)
        #pragma unroll
        for (int fn = 0; fn < 8; ++fn)
            #pragma unroll
            for (int q = 0; q < 4; ++q) acc[fm][fn][q] = 0.f;

    constexpr int CHUNKS = KDIM / 16;

    auto issue = [&](int c) {
        if (c < CHUNKS) {
            const int k0 = c * 16;
            const uint32_t sb = (uint32_t)(c & 1) * STG2_B;
            cpa16(dA + sb + A_HI_OFF,  g_ahi + aSrc + k0);
            cpa16(dA + sb + A_LO_OFF,  g_alo + aSrc + k0);
            cpa16(dB0 + sb + B_HI_OFF, Whi + bSrc0 + k0);
            cpa16(dB0 + sb + B_LO_OFF, Wlo + bSrc0 + k0);
            cpa16(dB1 + sb + B_HI_OFF, Whi + bSrc1 + k0);
            cpa16(dB1 + sb + B_LO_OFF, Wlo + bSrc1 + k0);
        }
        CPA_COMMIT();
    };

    issue(0);

    // fragment smem byte offsets (within an array), fixed per thread
    int offA[4][4], offB[8][2];
    #pragma unroll
    for (int fm = 0; fm < 4; ++fm) {
        int r0 = wm * 64 + fm * 16 + g;
        offA[fm][0] = swb(r0,     tig);
        offA[fm][1] = swb(r0 + 8, tig);
        offA[fm][2] = swb(r0,     tig + 4);
        offA[fm][3] = swb(r0 + 8, tig + 4);
    }
    #pragma unroll
    for (int fn = 0; fn < 8; ++fn) {
        int bn = wn * 64 + fn * 8 + g;
        offB[fn][0] = swb(bn, tig);
        offB[fn][1] = swb(bn, tig + 4);
    }

    for (int c = 0; c < CHUNKS; ++c) {
        if (c + 1 < CHUNKS) { issue(c + 1); cpa_wait<1>(); }
        else                { cpa_wait<0>(); }
        __syncthreads();

        const uint8_t* sb   = smem2 + (c & 1) * STG2_B;
        const uint8_t* sAhi = sb + A_HI_OFF;
        const uint8_t* sAlo = sb + A_LO_OFF;
        const uint8_t* sBhi = sb + B_HI_OFF;
        const uint8_t* sBlo = sb + B_LO_OFF;

        uint32_t af[2][4][4];
        #pragma unroll
        for (int fm = 0; fm < 4; ++fm)
            #pragma unroll
            for (int q = 0; q < 4; ++q) {
                af[0][fm][q] = *(const uint32_t*)(sAhi + offA[fm][q]);
                af[1][fm][q] = *(const uint32_t*)(sAlo + offA[fm][q]);
            }
        #pragma unroll
        for (int fn = 0; fn < 8; ++fn) {
            uint32_t bh0 = *(const uint32_t*)(sBhi + offB[fn][0]);
            uint32_t bh1 = *(const uint32_t*)(sBhi + offB[fn][1]);
            uint32_t bl0 = *(const uint32_t*)(sBlo + offB[fn][0]);
            uint32_t bl1 = *(const uint32_t*)(sBlo + offB[fn][1]);
            #pragma unroll
            for (int fm = 0; fm < 4; ++fm) {
                mma_bf16(acc[fm][fn], af[0][fm], bh0, bh1);   // hi*hi
                mma_bf16(acc[fm][fn], af[0][fm], bl0, bl1);   // hi*lo
                mma_bf16(acc[fm][fn], af[1][fm], bh0, bh1);   // lo*hi
            }
        }
        __syncthreads();
    }

    // ---- epilogue ----------------------------------------------------------
    float* Cout = (MODE == 0) ? g_t : outC;
    #pragma unroll
    for (int fm = 0; fm < 4; ++fm) {
        size_t r0 = rowBase + wm * 64 + fm * 16 + g;
        size_t r1 = r0 + 8;
        #pragma unroll
        for (int fn = 0; fn < 8; ++fn) {
            int col = n0 + wn * 64 + fn * 8 + 2 * tig;
            float2 v0, v1;
            if (MODE == 0) {
                v0.x = acc[fm][fn][0]; v0.y = acc[fm][fn][1];
                v1.x = acc[fm][fn][2]; v1.y = acc[fm][fn][3];
            } else {
                float bx = bias[col], by = bias[col + 1];
                v0.x = tanhf(acc[fm][fn][0] + bx);
                v0.y = tanhf(acc[fm][fn][1] + by);
                v1.x = tanhf(acc[fm][fn][2] + bx);
                v1.y = tanhf(acc[fm][fn][3] + by);
            }
            *(float2*)(Cout + r0 * HH + col) = v0;
            *(float2*)(Cout + r1 * HH + col) = v1;
        }
    }
}

// ---------------- per-graph aggregation -------------------------------------
template<int L>
__global__ void __launch_bounds__(64) agg_k(
    const int* __restrict__ src, const int* __restrict__ dst,
    const float* __restrict__ bias)
{
    __shared__ float sIn [TT * CH];
    __shared__ float sAcc[TT * CH];
    __shared__ float sNorm[EPG];
    __shared__ float sSelf[TT];
    __shared__ int   sSrc[EPG];
    __shared__ int   sDst[EPG];

    float* pout = (L == 0) ? g_p1 : (L == 1) ? g_p2 : g_p3;

    const int b   = blockIdx.x;
    const int c0  = blockIdx.y * CH;
    const int tid = threadIdx.x;

    const float* base = g_t + (size_t)b * TT * HH + c0;
    for (int i = tid; i < TT * CH; i += 64) {
        int node = i / CH, c = i & (CH - 1);
        sIn[i]  = base[(size_t)node * HH + c];
        sAcc[i] = 0.f;
    }
    for (int e = tid; e < EPG; e += 64) {
        sSrc[e]  = src[b * EPG + e] - b * TT;
        sDst[e]  = dst[b * EPG + e] - b * TT;
        sNorm[e] = g_norm[b * EPG + e];
    }
    for (int i = tid; i < TT; i += 64) {
        float d = g_dinv[b * TT + i];
        sSelf[i] = d * d;
    }
    __syncthreads();

    const int c = tid;
    #pragma unroll 4
    for (int e = 0; e < EPG; ++e) {
        sAcc[sDst[e] * CH + c] += sIn[sSrc[e] * CH + c] * sNorm[e];
    }

    const float bc = bias[c0 + c];
    float sum = 0.f, sq = 0.f;
    for (int node = 0; node < TT; ++node) {
        float v = sAcc[node * CH + c] + sIn[node * CH + c] * sSelf[node] + bc;
        pout[(size_t)(b * TT + node) * HH + c0 + c] = v;
        sum += v;
        sq  += v * v;
    }
    atomicAdd(&g_stats[c0 + c], sum);
    atomicAdd(&g_stats[HH + c0 + c], sq);
}

// ---------------- BN finalize ------------------------------------------------
template<int L>
__global__ void bnfinal_k(const float* __restrict__ g, const float* __restrict__ be)
{
    int c = threadIdx.x;
    float s = g_stats[c], sq = g_stats[HH + c];
    const float inv = 1.0f / (float)NN;
    float mean = s * inv;
    float var  = sq * inv - mean * mean;
    float rstd = rsqrtf(var + 1e-5f);
    float scl  = g[c] * rstd;
    g_scale[L * HH + c] = scl;
    g_shift[L * HH + c] = fmaf(-mean, scl, be[c]);
    g_stats[c] = 0.f;
    g_stats[HH + c] = 0.f;
}

// ---------------- host driver: kernel launches ONLY --------------------------
extern "C" void kernel_launch(void* const* d_in, const int* in_sizes, int n_in,
                              void* d_out, int out_size)
{
    (void)in_sizes; (void)n_in; (void)out_size;

    const float* x      = (const float*)d_in[0];
    const int*   eidx   = (const int*)  d_in[1];
    const int*   esrc   = eidx;
    const int*   edst   = eidx + EE;
    const float* ew     = (const float*)d_in[2];
    const int*   pos    = (const int*)  d_in[3];
    const float* posemb = (const float*)d_in[4];
    const float* W1 = (const float*)d_in[5];
    const float* b1 = (const float*)d_in[6];
    const float* g1 = (const float*)d_in[7];
    const float* be1= (const float*)d_in[8];
    const float* W2 = (const float*)d_in[9];
    const float* b2 = (const float*)d_in[10];
    const float* g2 = (const float*)d_in[11];
    const float* be2= (const float*)d_in[12];
    const float* W3 = (const float*)d_in[13];
    const float* b3 = (const float*)d_in[14];
    const float* g3 = (const float*)d_in[15];
    const float* be3= (const float*)d_in[16];
    const float* Wl = (const float*)d_in[17];
    const float* bl = (const float*)d_in[18];
    float* out = (float*)d_out;

    dim3 aGrid(NB, HH / CH);          // (2048, 8)
    dim3 gGrid(HH / 256, NN / 128);   // (2, 800)
    const int SPLIT_BLOCKS = (NN * HH / 4) / 256;   // 51200

    // prep ordered so gemm1 is launch index 3 (profiled slot)
    concat_split_k<<<NN, KIN>>>(x, pos, posemb);          // 0
    wprep_k<0, KIN><<<HH, 256>>>(W1);                     // 1
    wprep_k<1, HH><<<HH, 256>>>(W2);                      // 2
    gemm_hmma<0, KIN, 0><<<gGrid, 256>>>(nullptr, nullptr);  // 3
    deg_init_k<<<(NN + 255) / 256, 256>>>();              // 4
    deg_acc_k<<<(EE + 255) / 256, 256>>>(edst, ew);       // 5
    dinv_k<<<(NN + 255) / 256, 256>>>();                  // 6
    norm_k<<<(EE + 255) / 256, 256>>>(esrc, edst, ew);    // 7
    wprep_k<2, HH><<<HH, 256>>>(W3);                      // 8
    wprep_k<3, HH><<<HH, 256>>>(Wl);                      // 9

    // layer 1 aggregation + BN
    agg_k<0><<<aGrid, 64>>>(esrc, edst, b1);
    bnfinal_k<0><<<1, HH>>>(g1, be1);
    asplit_k<0><<<SPLIT_BLOCKS, 256>>>();

    // layer 2
    gemm_hmma<0, HH, 1><<<gGrid, 256>>>(nullptr, nullptr);
    agg_k<1><<<aGrid, 64>>>(esrc, edst, b2);
    bnfinal_k<1><<<1, HH>>>(g2, be2);
    asplit_k<1><<<SPLIT_BLOCKS, 256>>>();

    // layer 3
    gemm_hmma<0, HH, 2><<<gGrid, 256>>>(nullptr, nullptr);
    agg_k<2><<<aGrid, 64>>>(esrc, edst, b3);
    bnfinal_k<2><<<1, HH>>>(g3, be3);

    // residual combine + final head
    combine_split_k<<<SPLIT_BLOCKS, 256>>>();
    gemm_hmma<1, HH, 3><<<gGrid, 256>>>(out, bl);
}